// round 10
// baseline (speedup 1.0000x reference)
#include <cuda_runtime.h>
#include <math.h>

#define BB 128
#define TT 512
#define EE 256
#define HH 128
#define VV 32000
#define G4 512    // 4*H
#define UTPAD 68  // transposed-U smem pitch (floats): conflict-free LDS.128

// Scratch: xw[dir][t][b][4H]  (time-major input projections), 256 MiB
__device__ float g_xw[(size_t)2 * TT * BB * G4];

__device__ __forceinline__ float sigmoidf_(float x) {
    return 1.0f / (1.0f + expf(-x));
}

// packed fp32x2 FMA: acc.{lo,hi} += a.{lo,hi} * b.{lo,hi}   (Blackwell-only)
#define FMA2(acc, a, b) \
    asm("fma.rn.f32x2 %0, %1, %2, %0;" : "+l"(acc) : "l"(a), "l"(b))
#define UNPACK2(lo, hi, v) \
    asm("mov.b64 {%0, %1}, %2;" : "=f"(lo), "=f"(hi) : "l"(v))
#define PACK2(v, lo, hi) \
    asm("mov.b64 %0, {%1, %2};" : "=l"(v) : "f"(lo), "f"(hi))

// ---------------------------------------------------------------------------
// Kernel 1: fused embedding gather + input projection GEMM (f32x2 path).
// C[m,n] = sum_k emb[tok(m)][k] * W_d[k][n%512]; 128x128 tile, K-step 8,
// 256 threads, 8x8 microtile computed as 8x(4 column-pairs) with fma.rn.f32x2.
// A is staged in smem PRE-DUPLICATED {a,a} so the packed multiply needs no
// per-iteration register packs.
// ---------------------------------------------------------------------------
__global__ __launch_bounds__(256) void embed_proj_kernel(
    const void* __restrict__ tokens_raw,   // [B, T] int32 or int64
    const float* __restrict__ emb,         // [V, E]
    const float* __restrict__ W_fw,        // [E, 4H]
    const float* __restrict__ W_bw)        // [E, 4H]
{
    __shared__ __align__(16) float As2[8][256];   // duplicated pairs {a,a}
    __shared__ __align__(16) float Bs[8][128];
    __shared__ int srow[128];
    __shared__ int s_is64;

    const int tid = threadIdx.x;
    const int t   = blockIdx.y;
    const int n0  = blockIdx.x * 128;
    const int d   = n0 >> 9;
    const int nn0 = n0 & 511;
    const float* __restrict__ W = d ? W_bw : W_fw;

    if (tid == 0) {
        const int* ti = (const int*)tokens_raw;
        int is64 = 1;
#pragma unroll
        for (int q = 1; q < 64; q += 2) is64 &= (ti[q] == 0);
        s_is64 = is64;
    }
    __syncthreads();
    if (tid < 128) {
        int tok;
        if (s_is64) tok = (int)((const long long*)tokens_raw)[(size_t)tid * TT + t];
        else        tok = ((const int*)tokens_raw)[(size_t)tid * TT + t];
        tok = tok < 0 ? 0 : (tok >= VV ? VV - 1 : tok);
        srow[tid] = tok;
    }
    __syncthreads();

    const int ry = (tid >> 4) << 3;        // output row base
    const int cx = (tid & 15) << 3;        // output col base
    const int ai = tid >> 1;               // A-load row
    const int ak = (tid & 1) << 2;         // A-load k sub
    const int bk = tid >> 5;               // B-load k
    const int bn = (tid & 31) << 2;        // B-load col

    const float* aSrc = emb + (size_t)srow[ai] * EE + ak;
    const float* bSrc = W + (size_t)bk * G4 + nn0 + bn;

    unsigned long long acc2[8][4];         // {col 2p, col 2p+1} packed fp32x2
#pragma unroll
    for (int i = 0; i < 8; i++)
#pragma unroll
        for (int p = 0; p < 4; p++) acc2[i][p] = 0ULL;

    for (int k0 = 0; k0 < EE; k0 += 8) {
        float4 av = *(const float4*)(aSrc + k0);
        float4 bv = *(const float4*)(bSrc + (size_t)k0 * G4);
        __syncthreads();
        *(float2*)&As2[ak + 0][2 * ai] = make_float2(av.x, av.x);
        *(float2*)&As2[ak + 1][2 * ai] = make_float2(av.y, av.y);
        *(float2*)&As2[ak + 2][2 * ai] = make_float2(av.z, av.z);
        *(float2*)&As2[ak + 3][2 * ai] = make_float2(av.w, av.w);
        *(float4*)&Bs[bk][bn] = bv;
        __syncthreads();
#pragma unroll
        for (int kk = 0; kk < 8; kk++) {
            ulonglong2 bA = *(const ulonglong2*)&Bs[kk][cx];
            ulonglong2 bB = *(const ulonglong2*)&Bs[kk][cx + 4];
            unsigned long long ad[8];
#pragma unroll
            for (int i = 0; i < 8; i++)
                ad[i] = *(const unsigned long long*)&As2[kk][2 * (ry + i)];
#pragma unroll
            for (int i = 0; i < 8; i++) {
                FMA2(acc2[i][0], ad[i], bA.x);
                FMA2(acc2[i][1], ad[i], bA.y);
                FMA2(acc2[i][2], ad[i], bB.x);
                FMA2(acc2[i][3], ad[i], bB.y);
            }
        }
    }

    float* xw = g_xw + (size_t)d * (TT * BB) * G4;
#pragma unroll
    for (int i = 0; i < 8; i++) {
        size_t row = (size_t)t * BB + (ry + i);
        float* dst = xw + row * G4 + (nn0 + cx);
        ulonglong2 v0; v0.x = acc2[i][0]; v0.y = acc2[i][1];
        ulonglong2 v1; v1.x = acc2[i][2]; v1.y = acc2[i][3];
        *(ulonglong2*)(dst)     = v0;    // bitwise == 4 floats
        *(ulonglong2*)(dst + 4) = v1;
    }
}

// ---------------------------------------------------------------------------
// Kernel 2: recurrence. Grid (64, 2) = 128 independent blocks, 512 threads.
// Thread j owns z-column j for both batch rows. U rows 0..63 live in
// REGISTERS as k-pairs (zero crossbar traffic); rows 64..127 live TRANSPOSED
// in smem (shUT[j][k], pad 68 -> conflict-free LDS.128 over 4 consecutive k).
// All dot-product FMAs are fma.rn.f32x2 over k-pairs; one horizontal add
// per step folds the even/odd partial sums.
// ---------------------------------------------------------------------------
__global__ __launch_bounds__(512) void lstm_kernel(
    const float* __restrict__ U_fw, const float* __restrict__ bias_fw,
    const float* __restrict__ U_bw, const float* __restrict__ bias_bw,
    float* __restrict__ out, int has_states)
{
    extern __shared__ __align__(16) float smem[];
    float* shUT = smem;                     // 512 * UTPAD (rows 64..127, transposed)
    float* sh_h = smem + 512 * UTPAD;       // 2 * 128
    float* sh_z = sh_h + 2 * HH;            // 2 * 512

    const int tid = threadIdx.x;
    const int d   = blockIdx.y;
    const int b0  = blockIdx.x * 2;
    const float* __restrict__ U    = d ? U_bw : U_fw;
    const float* __restrict__ bias = d ? bias_bw : bias_fw;

    // Transposed load of U rows 64..127 into smem (coalesced LDG, one-time).
    for (int idx = tid; idx < 64 * G4; idx += 512) {
        int k = (idx >> 9) + 64;
        int jj = idx & 511;
        shUT[jj * UTPAD + (k - 64)] = U[(size_t)k * G4 + jj];
    }

    const int j = tid;
    // U rows 0..63 as register-resident k-pairs {u[2p], u[2p+1]}.
    unsigned long long uregd[32];
#pragma unroll
    for (int p = 0; p < 32; p++) {
        float lo = U[(size_t)(2 * p) * G4 + j];
        float hi = U[(size_t)(2 * p + 1) * G4 + j];
        PACK2(uregd[p], lo, hi);
    }

    if (tid < 2 * HH) sh_h[tid] = 0.0f;
    __syncthreads();

    const float bias_j = bias[j];
    const int grow = tid >> 7;              // gate-phase row (threads 0..255)
    const int gjh  = tid & 127;
    float cst = 0.0f;

    const float* xwbase = g_xw + (size_t)d * (TT * BB) * G4;
    const float* shUTj = shUT + (size_t)j * UTPAD;
    const int tstart = d ? (TT - 1) : 0;
    const int tinc   = d ? -1 : 1;

    int t = tstart;
    for (int s = 0; s < TT; s++, t += tinc) {
        const float xa0 = xwbase[((size_t)t * BB + b0 + 0) * G4 + j];
        const float xa1 = xwbase[((size_t)t * BB + b0 + 1) * G4 + j];

        unsigned long long p0 = 0ULL, p1 = 0ULL;  // packed even/odd partials

        // k = 0..63: register-resident U
#pragma unroll
        for (int c = 0; c < 16; c++) {
            ulonglong2 h0 = *(const ulonglong2*)&sh_h[4 * c];
            ulonglong2 h1 = *(const ulonglong2*)&sh_h[HH + 4 * c];
            FMA2(p0, h0.x, uregd[2 * c + 0]);
            FMA2(p0, h0.y, uregd[2 * c + 1]);
            FMA2(p1, h1.x, uregd[2 * c + 0]);
            FMA2(p1, h1.y, uregd[2 * c + 1]);
        }
        // k = 64..127: transposed smem U (conflict-free LDS.128)
#pragma unroll
        for (int c = 0; c < 16; c++) {
            ulonglong2 uv = *(const ulonglong2*)&shUTj[4 * c];
            ulonglong2 h0 = *(const ulonglong2*)&sh_h[64 + 4 * c];
            ulonglong2 h1 = *(const ulonglong2*)&sh_h[HH + 64 + 4 * c];
            FMA2(p0, h0.x, uv.x);
            FMA2(p0, h0.y, uv.y);
            FMA2(p1, h1.x, uv.x);
            FMA2(p1, h1.y, uv.y);
        }

        float p0lo, p0hi, p1lo, p1hi;
        UNPACK2(p0lo, p0hi, p0);
        UNPACK2(p1lo, p1hi, p1);
        sh_z[j]      = (bias_j + xa0) + (p0lo + p0hi);
        sh_z[G4 + j] = (bias_j + xa1) + (p1lo + p1hi);
        __syncthreads();  // z complete; orders old-h reads before new-h writes

        if (tid < 256) {
            const float* zr = sh_z + grow * G4;
            float zi = zr[gjh];
            float zf = zr[128 + gjh];
            float zg = zr[256 + gjh];
            float zo = zr[384 + gjh];
            float ig = sigmoidf_(zi), fg = sigmoidf_(zf);
            float gg = tanhf(zg),     og = sigmoidf_(zo);
            cst = fg * cst + ig * gg;
            float h = og * tanhf(cst);
            sh_h[grow * HH + gjh] = h;
            out[((size_t)(b0 + grow) * TT + t) * 256 + d * 128 + gjh] = h;
        }
        __syncthreads();  // new h visible before next step
    }

    // Final states: out_tail = [h_fw, c_fw, h_bw, c_bw], each [B, H]
    if (has_states && tid < 256) {
        float* st = out + (size_t)BB * TT * 256 + (size_t)d * 2 * BB * HH;
        st[(b0 + grow) * HH + gjh] = sh_h[grow * HH + gjh];
        st[(size_t)BB * HH + (b0 + grow) * HH + gjh] = cst;
    }
}

// ---------------------------------------------------------------------------
extern "C" void kernel_launch(void* const* d_in, const int* in_sizes, int n_in,
                              void* d_out, int out_size)
{
    const void*  tokens = d_in[0];
    const float* emb  = (const float*)d_in[1];
    const float* W_fw = (const float*)d_in[2];
    const float* U_fw = (const float*)d_in[3];
    const float* b_fw = (const float*)d_in[4];
    const float* W_bw = (const float*)d_in[5];
    const float* U_bw = (const float*)d_in[6];
    const float* b_bw = (const float*)d_in[7];
    float* out = (float*)d_out;

    // Kernel 1: xw = embed(tokens) @ [W_fw | W_bw]
    dim3 g1(8, 512);
    embed_proj_kernel<<<g1, 256>>>(tokens, emb, W_fw, W_bw);

    // Kernel 2: bidirectional recurrence (141 KB dynamic smem)
    const int smem_bytes = (512 * UTPAD + 2 * HH + 2 * G4) * (int)sizeof(float);
    cudaFuncSetAttribute((const void*)lstm_kernel,
                         cudaFuncAttributeMaxDynamicSharedMemorySize, smem_bytes);
    const long long full = (long long)BB * TT * 256 + 4LL * BB * HH;
    int has_states = ((long long)out_size >= full) ? 1 : 0;
    dim3 g2(64, 2);
    lstm_kernel<<<g2, 512, smem_bytes>>>(U_fw, b_fw, U_bw, b_bw, out, has_states);
}